// round 1
// baseline (speedup 1.0000x reference)
#include <cuda_runtime.h>
#include <cstdint>

#define NV     8192
#define NT     1000
#define UNITS  20
#define IND    12
#define NCOL   80          // 4*UNITS
#define VPG    8           // vehicles per group
#define TPG    80          // threads per group: one per (unit,gate) column
#define GPB    2           // groups per block
#define THREADS (GPB*TPG)  // 160
#define BLOCKS  (NV/(GPB*VPG)) // 512

// output packing (flat concat in reference return order)
#define OUT_POS 0
#define OUT_LC  (NV*NT)                       // 8192000
#define OUT_SPD (OUT_LC + NV*NT*3)            // 32768000
#define OUT_H   (OUT_SPD + NV)                // 32776192
#define OUT_C   (OUT_H + NV*UNITS)            // 32940032

__device__ __forceinline__ unsigned long long pk(float x, float y) {
    unsigned long long r;
    asm("mov.b64 %0, {%1,%2};" : "=l"(r) : "f"(x), "f"(y));
    return r;
}
__device__ __forceinline__ float2 unpk(unsigned long long v) {
    float2 f;
    asm("mov.b64 {%0,%1}, %2;" : "=f"(f.x), "=f"(f.y) : "l"(v));
    return f;
}
__device__ __forceinline__ void ffma2(unsigned long long& d, unsigned long long a, unsigned long long b) {
    asm("fma.rn.f32x2 %0, %1, %2, %0;" : "+l"(d) : "l"(a), "l"(b));
}

__device__ __forceinline__ float sigf(float x) {
    return __fdividef(1.0f, 1.0f + __expf(-x));
}
__device__ __forceinline__ float tanh_ex(float x) {
    // tanh(x) = 2*sigmoid(2x) - 1  (EX2+RCP based, ~1e-6 abs err)
    return fmaf(2.0f, sigf(2.0f * x), -1.0f);
}
__device__ __forceinline__ float nanfix(float v) {
    return (v == v) ? v : 1.0f;
}

__global__ void __launch_bounds__(THREADS, 4)
rnncf_kernel(const float* __restrict__ inp,        // (NV, NT, 12)
             const float* __restrict__ init_state, // (NV, 2)
             const float* __restrict__ h0,         // (NV, 20)
             const float* __restrict__ c0,         // (NV, 20)
             const float* __restrict__ Wk,         // (12, 80)
             const float* __restrict__ Wr,         // (20, 80)
             const float* __restrict__ bz,         // (80)
             const float* __restrict__ d2w,        // (20, 10)
             const float* __restrict__ d2b,        // (10)
             const float* __restrict__ lcw,        // (10, 3)
             const float* __restrict__ lcb,        // (3)
             const float* __restrict__ d1w,        // (10, 1)
             const float* __restrict__ d1b,        // (1)
             float* __restrict__ out)
{
    // smem
    __shared__ float4 xin[GPB][VPG][8];        // [cur(12) | h(20)] as 8 float4 per vehicle
    __shared__ float4 acts[GPB][VPG][UNITS];   // per (v,u): [sig(i), sig(f), tanh(g), sig(o)]
    __shared__ float  xs[GPB][VPG][10];        // head activations
    __shared__ float  s_d2t[10][UNITS];        // d2w transposed: [col][k]
    __shared__ float  s_d2b[10];
    __shared__ float  s_lcw[10][3];
    __shared__ float  s_lcb[3];
    __shared__ float  s_d1w[10];
    __shared__ float  s_d1b;

    const int tid = threadIdx.x;
    const int grp = tid / TPG;
    const int j   = tid % TPG;      // weight column 0..79
    const int g   = j / UNITS;      // gate: 0=i 1=f 2=g 3=o
    const int u   = j % UNITS;      // unit
    const int vbase = blockIdx.x * (GPB * VPG) + grp * VPG;

    // head weights -> smem
    for (int i = tid; i < 200; i += THREADS) {
        int k = i / 10, c = i % 10;
        s_d2t[c][k] = d2w[i];
    }
    if (tid < 10) s_d2b[tid] = d2b[tid];
    if (tid < 30) s_lcw[tid / 3][tid % 3] = lcw[tid];
    if (tid < 3)  s_lcb[tid] = lcb[tid];
    if (tid < 10) s_d1w[tid] = d1w[tid];
    if (tid == 0) s_d1b = d1b[0];

    // per-thread LSTM weight column as 16 f32x2 pairs (register-resident)
    unsigned long long w2[16];
    const float biasj = bz[j];
#pragma unroll
    for (int p = 0; p < 16; p++) {
        int k0 = 2 * p, k1 = 2 * p + 1;
        float wa = (k0 < IND) ? Wk[k0 * NCOL + j] : Wr[(k0 - IND) * NCOL + j];
        float wb = (k1 < IND) ? Wk[k1 * NCOL + j] : Wr[(k1 - IND) * NCOL + j];
        w2[p] = pk(wa, wb);
    }

    // state
    float c_reg[VPG];
#pragma unroll
    for (int v = 0; v < VPG; v++) c_reg[v] = 0.0f;
    float pos = 0.0f, spd = 0.0f;
    float4 pre0 = {0,0,0,0}, pre1 = {0,0,0,0}, pre2 = {0,0,0,0};

    if (g == 0) {
#pragma unroll
        for (int v = 0; v < VPG; v++) {
            int vg = vbase + v;
            ((float*)&xin[grp][v])[12 + u] = h0[vg * UNITS + u];
            c_reg[v] = c0[vg * UNITS + u];
        }
    }
    if (g == 3 && u < VPG) {
        int vg = vbase + u;
        pos = init_state[vg * 2 + 0];
        spd = init_state[vg * 2 + 1];
        const float4* ip = (const float4*)(inp + (size_t)vg * NT * 12);
        pre0 = ip[0]; pre1 = ip[1]; pre2 = ip[2];   // prefetch t=0
    }
    __syncthreads();

    for (int t = 0; t < NT; t++) {
        // ---- P1: build normalized inputs cur[12] (uses pre-update pos) ----
        if (g == 3 && u < VPG) {
            const int v = u;
            float* xr = (float*)&xin[grp][v];
            const float ih = 0.01f;          // 1/MAXHD
            const float iv = 0.025f;         // 1/MAXV
            xr[0]  = nanfix((pre0.x - pos) * ih);
            xr[1]  = nanfix((pre0.y - pos) * ih);
            xr[2]  = nanfix((pre0.z - pos) * ih);
            xr[3]  = nanfix((pos - pre0.w) * ih);
            xr[4]  = nanfix((pos - pre1.x) * ih);
            xr[5]  = nanfix((pos - pre1.y) * ih);
            xr[6]  = nanfix(pre1.z * iv);
            xr[7]  = nanfix(pre1.w * iv);
            xr[8]  = nanfix(pre2.x * iv);
            xr[9]  = nanfix(pre2.y * iv);
            xr[10] = nanfix(pre2.z * iv);
            xr[11] = nanfix(pre2.w * iv);
            if (t + 1 < NT) {   // prefetch next step's raw inputs
                const float4* ip = (const float4*)(inp + ((size_t)(vbase + v) * NT + (t + 1)) * 12);
                pre0 = ip[0]; pre1 = ip[1]; pre2 = ip[2];
            }
        }
        __syncthreads();

        // ---- P3: z = [cur|h] . w_col + b, then activation ----
#pragma unroll
        for (int v = 0; v < VPG; v++) {
            const float4* xr4 = &xin[grp][v][0];
            unsigned long long a0 = pk(biasj, 0.0f);
            unsigned long long a1 = pk(0.0f, 0.0f);
#pragma unroll
            for (int q = 0; q < 8; q += 2) {
                float4 A = xr4[q];
                ffma2(a0, pk(A.x, A.y), w2[2 * q]);
                ffma2(a0, pk(A.z, A.w), w2[2 * q + 1]);
                float4 B = xr4[q + 1];
                ffma2(a1, pk(B.x, B.y), w2[2 * q + 2]);
                ffma2(a1, pk(B.z, B.w), w2[2 * q + 3]);
            }
            float2 fa = unpk(a0), fb = unpk(a1);
            float z = (fa.x + fa.y) + (fb.x + fb.y);
            float a = (g == 2) ? tanh_ex(z) : sigf(z);
            ((float*)&acts[grp][v][u])[g] = a;
        }
        __syncthreads();

        // ---- P5: LSTM cell update (one thread per unit) ----
        if (g == 0) {
#pragma unroll
            for (int v = 0; v < VPG; v++) {
                float4 A = acts[grp][v][u];   // [si, sf, tg, so]
                float c = fmaf(A.y, c_reg[v], A.x * A.z);
                c_reg[v] = c;
                float h = A.w * tanh_ex(c);
                ((float*)&xin[grp][v])[12 + u] = h;
            }
        }
        __syncthreads();

        // ---- P7: x = relu(h @ d2w + d2b) (10 threads) ----
        if (g == 1 && u < 10) {
            unsigned long long wd[10];
            const float4* wrow = (const float4*)&s_d2t[u][0];
#pragma unroll
            for (int m = 0; m < 5; m++) {
                float4 W = wrow[m];
                wd[2 * m]     = pk(W.x, W.y);
                wd[2 * m + 1] = pk(W.z, W.w);
            }
            float db = s_d2b[u];
#pragma unroll
            for (int v = 0; v < VPG; v++) {
                const float4* hr = (const float4*)(((float*)&xin[grp][v]) + 12);
                unsigned long long a0 = pk(db, 0.0f);
                unsigned long long a1 = pk(0.0f, 0.0f);
#pragma unroll
                for (int m = 0; m < 5; m++) {
                    float4 H = hr[m];
                    ffma2((m & 1) ? a1 : a0, pk(H.x, H.y), wd[2 * m]);
                    ffma2((m & 1) ? a1 : a0, pk(H.z, H.w), wd[2 * m + 1]);
                }
                float2 fa = unpk(a0), fb = unpk(a1);
                float x = (fa.x + fa.y) + (fb.x + fb.y);
                xs[grp][v][u] = fmaxf(x, 0.0f);
            }
        }
        __syncthreads();

        // ---- P9: lc, acc, integrate, store outputs ----
        if (g == 3 && u < VPG) {
            const int v = u;
            const int vg = vbase + v;
            float l0 = s_lcb[0], l1 = s_lcb[1], l2 = s_lcb[2], ar = s_d1b;
#pragma unroll
            for (int m = 0; m < 10; m++) {
                float xm = xs[grp][v][m];
                l0 = fmaf(xm, s_lcw[m][0], l0);
                l1 = fmaf(xm, s_lcw[m][1], l1);
                l2 = fmaf(xm, s_lcw[m][2], l2);
                ar = fmaf(xm, s_d1w[m], ar);
            }
            float acc = fmaf(10.0f, ar, -6.0f);      // (MAXA-MINA)*raw + MINA
            pos = fmaf(0.1f, spd, pos);
            spd = fmaf(0.1f, acc, spd);
            out[OUT_POS + (size_t)vg * NT + t] = pos;
            float* lco = out + OUT_LC + ((size_t)vg * NT + t) * 3;
            lco[0] = l0; lco[1] = l1; lco[2] = l2;
        }
        // next P1 (same threads) only touches its own state + xin[0..11];
        // the first barrier of the next iteration orders it vs P3 readers.
    }

    // ---- finals ----
    if (g == 3 && u < VPG) {
        out[OUT_SPD + vbase + u] = spd;
    }
    if (g == 0) {
#pragma unroll
        for (int v = 0; v < VPG; v++) {
            int vg = vbase + v;
            out[OUT_H + (size_t)vg * UNITS + u] = ((float*)&xin[grp][v])[12 + u];
            out[OUT_C + (size_t)vg * UNITS + u] = c_reg[v];
        }
    }
}

extern "C" void kernel_launch(void* const* d_in, const int* in_sizes, int n_in,
                              void* d_out, int out_size) {
    const float* inp        = (const float*)d_in[0];
    const float* init_state = (const float*)d_in[1];
    const float* h0         = (const float*)d_in[2];
    const float* c0         = (const float*)d_in[3];
    const float* Wk         = (const float*)d_in[4];
    const float* Wr         = (const float*)d_in[5];
    const float* bzv        = (const float*)d_in[6];
    const float* d2w        = (const float*)d_in[7];
    const float* d2b        = (const float*)d_in[8];
    const float* lcw        = (const float*)d_in[9];
    const float* lcb        = (const float*)d_in[10];
    const float* d1w        = (const float*)d_in[11];
    const float* d1b        = (const float*)d_in[12];
    float* out = (float*)d_out;

    rnncf_kernel<<<BLOCKS, THREADS>>>(inp, init_state, h0, c0, Wk, Wr, bzv,
                                      d2w, d2b, lcw, lcb, d1w, d1b, out);
}